// round 14
// baseline (speedup 1.0000x reference)
#include <cuda_runtime.h>
#include <cuda_bf16.h>
#include <cuda_fp16.h>
#include <cstdint>

#define N_NODES 100000
#define N_PAD 100096                 // padded rows for unpredicated A loads
#define N_EDGES 800000
#define IN_SIZE 256
#define OUT_SIZE 256
#define NBLK_SCAN ((N_NODES + 1023) / 1024)   // 98

// ---------------------------------------------------------------------------
// Device scratch
// ---------------------------------------------------------------------------
__device__ __align__(128) __half g_x_h[(size_t)N_PAD * IN_SIZE];          // X fp16 (padded)
__device__ __align__(128) __half g_supp_h[(size_t)N_NODES * OUT_SIZE];    // x @ W (fp16)
__device__ __align__(128) __half g_w_h[IN_SIZE * OUT_SIZE];               // W fp16 [k][n]

__device__ int   g_deg[N_NODES];
__device__ int   g_loc[N_NODES];
__device__ int   g_bsum[128];
__device__ int   g_off[N_NODES + 1];
__device__ int   g_cur[N_NODES];
__device__ __align__(16) uint2 g_edge[N_EDGES];   // {src, weight bits} grouped by dst

// ---------------------------------------------------------------------------
// Helpers
// ---------------------------------------------------------------------------
__device__ __forceinline__ uint32_t smem_u32(const void* p) {
    uint32_t a;
    asm("{ .reg .u64 t; cvta.to.shared.u64 t, %1; cvt.u32.u64 %0, t; }" : "=r"(a) : "l"(p));
    return a;
}
__device__ __forceinline__ void ldsm_x4(uint32_t* r, uint32_t addr) {
    asm volatile("ldmatrix.sync.aligned.m8n8.x4.shared.b16 {%0,%1,%2,%3}, [%4];"
                 : "=r"(r[0]), "=r"(r[1]), "=r"(r[2]), "=r"(r[3]) : "r"(addr));
}
__device__ __forceinline__ void ldsm_x4_t(uint32_t* r, uint32_t addr) {
    asm volatile("ldmatrix.sync.aligned.m8n8.x4.trans.shared.b16 {%0,%1,%2,%3}, [%4];"
                 : "=r"(r[0]), "=r"(r[1]), "=r"(r[2]), "=r"(r[3]) : "r"(addr));
}
__device__ __forceinline__ void mma_f16(float* d, const uint32_t* a, const uint32_t* b) {
    asm volatile(
        "mma.sync.aligned.m16n8k16.row.col.f32.f16.f16.f32 "
        "{%0,%1,%2,%3}, {%4,%5,%6,%7}, {%8,%9}, {%0,%1,%2,%3};"
        : "+f"(d[0]), "+f"(d[1]), "+f"(d[2]), "+f"(d[3])
        : "r"(a[0]), "r"(a[1]), "r"(a[2]), "r"(a[3]), "r"(b[0]), "r"(b[1]));
}
__device__ __forceinline__ uint32_t hpack(float x, float y) {
    __half2 t = __floats2half2_rn(x, y);
    return *reinterpret_cast<uint32_t*>(&t);
}
__device__ __forceinline__ void stcs_f4(float* p, float4 v) {
    asm volatile("st.global.cs.v4.f32 [%0], {%1,%2,%3,%4};"
                 :: "l"(p), "f"(v.x), "f"(v.y), "f"(v.z), "f"(v.w) : "memory");
}
__device__ __forceinline__ void cp16(uint32_t dst, const void* src) {
    asm volatile("cp.async.ca.shared.global [%0], [%1], 16;" :: "r"(dst), "l"(src));
}
#define CP_COMMIT() asm volatile("cp.async.commit_group;" ::: "memory")
#define CP_WAIT(n)  asm volatile("cp.async.wait_group %0;" :: "n"(n) : "memory")

__device__ __forceinline__ float2 h2f2(uint32_t u) {
    __half2 h = *reinterpret_cast<__half2*>(&u);
    return __half22float2(h);
}

// ---------------------------------------------------------------------------
// Prep: X fp32 -> fp16 (padded rows zeroed); W fp32 -> fp16
// ---------------------------------------------------------------------------
__global__ void prep_x_kernel(const float* __restrict__ X) {
    const int idx = blockIdx.x * blockDim.x + threadIdx.x;   // float4 units
    const int total = N_NODES * (IN_SIZE / 4);
    if (idx < total) {
        const float4 f = reinterpret_cast<const float4*>(X)[idx];
        reinterpret_cast<uint2*>(g_x_h)[idx] = make_uint2(hpack(f.x, f.y), hpack(f.z, f.w));
    } else if (idx < N_PAD * (IN_SIZE / 4)) {
        reinterpret_cast<uint2*>(g_x_h)[idx] = make_uint2(0u, 0u);
    }
}

__global__ void prep_w_kernel(const float* __restrict__ W) {
    const int idx = blockIdx.x * blockDim.x + threadIdx.x;
    g_w_h[idx] = __float2half_rn(W[idx]);
}

// ---------------------------------------------------------------------------
// GEMM half: supp[:, n_base:n_base+128] = Xh @ Wh[:, n_base:...]
// CTA 128(M)x128(N), warps 4(M)x2(N) -> warp tile 32x64, KC=32, 2 CTAs/SM,
// all-cp.async 3-stage pipeline.
// ---------------------------------------------------------------------------
#define KC 32
#define NCH (IN_SIZE / KC)   // 8
#define LDA 40    // fp16 per A smem row (32 + 8 pad) = 80 B
#define LDB 136   // fp16 per B smem row (128 + 8 pad) = 272 B

#define OFF_A  0
#define OFF_B  10240
#define STAGE  18944          // 10240 + 32*272
#define NSTAGE 3
#define GEMM_SMEM (NSTAGE * STAGE)   // 56832

__global__ __launch_bounds__(256, 2) void gemm_hmma_kernel(int n_base) {
    extern __shared__ __align__(16) char smem[];
    const uint32_t sb = smem_u32(smem);

    const int tid = threadIdx.x;
    const int lane = tid & 31;
    const int w = tid >> 5;
    const int wm = w >> 1;        // 0..3  (M)
    const int wn = w & 1;         // 0..1  (N)
    const int tile_n = n_base;
    const int tile_m = blockIdx.y * 128;

    float acc[2][8][4];
#pragma unroll
    for (int i = 0; i < 2; i++)
#pragma unroll
        for (int j = 0; j < 8; j++)
#pragma unroll
            for (int q = 0; q < 4; q++) acc[i][j][q] = 0.0f;

    const int lm_row = lane & 15;
    const int lm_coloff = (lane >> 4) * 8;

    auto issue = [&](int st) {
        const uint32_t buf = sb + (st % NSTAGE) * STAGE;
        const int k0 = st * KC;
#pragma unroll
        for (int i = 0; i < 2; i++) {
            const int idx = i * 256 + tid;
            const int row = idx >> 2;
            const int seg = idx & 3;
            cp16(buf + OFF_A + row * 80 + seg * 16,
                 &g_x_h[(size_t)(tile_m + row) * IN_SIZE + k0 + seg * 8]);
        }
#pragma unroll
        for (int i = 0; i < 2; i++) {
            const int idx = i * 256 + tid;
            const int row = idx >> 4;
            const int seg = idx & 15;
            cp16(buf + OFF_B + row * 272 + seg * 16,
                 &g_w_h[(size_t)(k0 + row) * OUT_SIZE + tile_n + seg * 8]);
        }
        CP_COMMIT();
    };

    issue(0);
    issue(1);

#pragma unroll
    for (int c = 0; c < NCH; c++) {
        if (c == NCH - 1) { CP_WAIT(0); } else { CP_WAIT(1); }
        __syncthreads();

        if (c + 2 < NCH) issue(c + 2);

        const uint32_t buf = sb + (c % NSTAGE) * STAGE;
        const uint32_t as = buf + OFF_A;
        const uint32_t bs = buf + OFF_B;

#pragma unroll
        for (int kk = 0; kk < 2; kk++) {
            const int ks = kk * 16;
            uint32_t am[2][4];
#pragma unroll
            for (int i = 0; i < 2; i++) {
                const uint32_t off =
                    ((uint32_t)(wm * 32 + i * 16 + lm_row) * LDA + ks + lm_coloff) * 2;
                ldsm_x4(am[i], as + off);
            }
            uint32_t bm[16];
#pragma unroll
            for (int jj = 0; jj < 4; jj++) {
                const uint32_t off =
                    ((uint32_t)(ks + lm_row) * LDB + wn * 64 + jj * 16 + lm_coloff) * 2;
                ldsm_x4_t(&bm[jj * 4], bs + off);
            }
#pragma unroll
            for (int i = 0; i < 2; i++)
#pragma unroll
                for (int j = 0; j < 8; j++)
                    mma_f16(acc[i][j], am[i], &bm[j * 2]);
        }
    }

    // ---- epilogue: fp16 stores
    const int er = lane >> 2;
    const int ec = (lane & 3) * 2;
#pragma unroll
    for (int i = 0; i < 2; i++) {
        const int r0 = tile_m + wm * 32 + i * 16 + er;
#pragma unroll
        for (int j = 0; j < 8; j++) {
            const int col = tile_n + wn * 64 + j * 8 + ec;
            if (r0 < N_NODES) {
                __half2 h = __floats2half2_rn(acc[i][j][0], acc[i][j][1]);
                *reinterpret_cast<__half2*>(&g_supp_h[(size_t)r0 * OUT_SIZE + col]) = h;
            }
            if (r0 + 8 < N_NODES) {
                __half2 h = __floats2half2_rn(acc[i][j][2], acc[i][j][3]);
                *reinterpret_cast<__half2*>(&g_supp_h[(size_t)(r0 + 8) * OUT_SIZE + col]) = h;
            }
        }
    }
}

// ---------------------------------------------------------------------------
// CSR build: zero -> histogram -> scan(3) -> fill
// ---------------------------------------------------------------------------
__global__ void zero_deg_kernel() {
    const int i = blockIdx.x * blockDim.x + threadIdx.x;
    if (i < N_NODES) g_deg[i] = 0;
}

__global__ void hist_kernel(const int* __restrict__ edst) {
    const int e = blockIdx.x * blockDim.x + threadIdx.x;
    if (e < N_EDGES) atomicAdd(&g_deg[edst[e]], 1);
}

__global__ __launch_bounds__(1024) void scan1_kernel() {
    __shared__ int s[1024];
    const int tid = threadIdx.x;
    const int i = blockIdx.x * 1024 + tid;
    const int v = (i < N_NODES) ? g_deg[i] : 0;
    s[tid] = v;
    __syncthreads();
#pragma unroll
    for (int d = 1; d < 1024; d <<= 1) {
        int t = (tid >= d) ? s[tid - d] : 0;
        __syncthreads();
        s[tid] += t;
        __syncthreads();
    }
    if (i < N_NODES) g_loc[i] = s[tid] - v;
    if (tid == 1023) g_bsum[blockIdx.x] = s[1023];
}

__global__ __launch_bounds__(128) void scan2_kernel() {
    __shared__ int s[128];
    const int tid = threadIdx.x;
    const int v = (tid < NBLK_SCAN) ? g_bsum[tid] : 0;
    s[tid] = v;
    __syncthreads();
#pragma unroll
    for (int d = 1; d < 128; d <<= 1) {
        int t = (tid >= d) ? s[tid - d] : 0;
        __syncthreads();
        s[tid] += t;
        __syncthreads();
    }
    g_bsum[tid] = s[tid] - v;
}

__global__ void scan3_kernel() {
    const int i = blockIdx.x * blockDim.x + threadIdx.x;
    if (i < N_NODES) {
        const int off = g_loc[i] + g_bsum[i >> 10];
        g_off[i] = off;
        g_cur[i] = off;
    }
    if (i == 0) g_off[N_NODES] = N_EDGES;
}

__global__ void fill_kernel(const float* __restrict__ ew,
                            const int* __restrict__ esrc,
                            const int* __restrict__ edst) {
    const int e = blockIdx.x * blockDim.x + threadIdx.x;
    if (e < N_EDGES) {
        const int p = atomicAdd(&g_cur[edst[e]], 1);
        g_edge[p] = make_uint2((uint32_t)esrc[e], __float_as_uint(ew[e]));
    }
}

// ---------------------------------------------------------------------------
// Aggregate half: one warp per dst node over 128 columns.
// out[d][col_base + lane*4 .. +4) = sum supp_h[src][...] * w + bias[...]
// ---------------------------------------------------------------------------
__global__ __launch_bounds__(256) void aggregate_kernel(const float* __restrict__ bias,
                                                        float* __restrict__ out,
                                                        int col_base) {
    const int d = (blockIdx.x * blockDim.x + threadIdx.x) >> 5;
    const int lane = threadIdx.x & 31;
    if (d >= N_NODES) return;

    const int beg = g_off[d];
    const int end = g_off[d + 1];
    const int col = col_base + lane * 4;

    float4 acc = reinterpret_cast<const float4*>(&bias[col])[0];

    int p = beg;
    for (; p + 1 < end; p += 2) {
        const uint2 e0 = g_edge[p];
        const uint2 e1 = g_edge[p + 1];
        const float w0 = __uint_as_float(e0.y);
        const float w1 = __uint_as_float(e1.y);
        const uint2 v0 = *reinterpret_cast<const uint2*>(
            &g_supp_h[(size_t)e0.x * OUT_SIZE + col]);
        const uint2 v1 = *reinterpret_cast<const uint2*>(
            &g_supp_h[(size_t)e1.x * OUT_SIZE + col]);

        float2 f;
        f = h2f2(v0.x); acc.x = fmaf(f.x, w0, acc.x); acc.y = fmaf(f.y, w0, acc.y);
        f = h2f2(v0.y); acc.z = fmaf(f.x, w0, acc.z); acc.w = fmaf(f.y, w0, acc.w);
        f = h2f2(v1.x); acc.x = fmaf(f.x, w1, acc.x); acc.y = fmaf(f.y, w1, acc.y);
        f = h2f2(v1.y); acc.z = fmaf(f.x, w1, acc.z); acc.w = fmaf(f.y, w1, acc.w);
    }
    if (p < end) {
        const uint2 e0 = g_edge[p];
        const float w0 = __uint_as_float(e0.y);
        const uint2 v0 = *reinterpret_cast<const uint2*>(
            &g_supp_h[(size_t)e0.x * OUT_SIZE + col]);
        float2 f;
        f = h2f2(v0.x); acc.x = fmaf(f.x, w0, acc.x); acc.y = fmaf(f.y, w0, acc.y);
        f = h2f2(v0.y); acc.z = fmaf(f.x, w0, acc.z); acc.w = fmaf(f.y, w0, acc.w);
    }

    stcs_f4(&out[(size_t)d * OUT_SIZE + col], acc);
}

// ---------------------------------------------------------------------------
extern "C" void kernel_launch(void* const* d_in, const int* in_sizes, int n_in,
                              void* d_out, int out_size) {
    const float* x      = (const float*)d_in[0];
    const float* weight = (const float*)d_in[1];
    const float* bias   = (const float*)d_in[2];
    const float* ew     = (const float*)d_in[3];
    const int*   esrc   = (const int*)d_in[4];
    const int*   edst   = (const int*)d_in[5];
    float* out = (float*)d_out;

    static cudaStream_t s2 = nullptr, s3 = nullptr;
    static cudaEvent_t evA = nullptr, evB = nullptr, evG0 = nullptr, evA0 = nullptr;
    if (!s2) {
        cudaStreamCreateWithFlags(&s2, cudaStreamNonBlocking);
        cudaStreamCreateWithFlags(&s3, cudaStreamNonBlocking);
        cudaEventCreateWithFlags(&evA, cudaEventDisableTiming);
        cudaEventCreateWithFlags(&evB, cudaEventDisableTiming);
        cudaEventCreateWithFlags(&evG0, cudaEventDisableTiming);
        cudaEventCreateWithFlags(&evA0, cudaEventDisableTiming);
        cudaFuncSetAttribute(gemm_hmma_kernel, cudaFuncAttributeMaxDynamicSharedMemorySize,
                             GEMM_SMEM);
    }

    cudaEventRecord(evA, 0);
    cudaStreamWaitEvent(s2, evA, 0);
    cudaStreamWaitEvent(s3, evA, 0);

    dim3 ggrid(1, (N_NODES + 127) / 128);
    const int agg_blocks = (N_NODES * 32 + 255) / 256;

    // main: prep + first GEMM half (gemm0 = 4th launch overall for ncu slot)
    prep_x_kernel<<<(N_PAD * (IN_SIZE / 4) + 255) / 256, 256>>>(x);         // 0 main
    prep_w_kernel<<<IN_SIZE * OUT_SIZE / 256, 256>>>(weight);               // 1 main
    zero_deg_kernel<<<(N_NODES + 255) / 256, 256, 0, s2>>>();               // 2 s2
    gemm_hmma_kernel<<<ggrid, 256, GEMM_SMEM>>>(0);                         // 3 main
    cudaEventRecord(evG0, 0);

    // s2: rest of CSR build
    hist_kernel<<<(N_EDGES + 255) / 256, 256, 0, s2>>>(edst);
    scan1_kernel<<<NBLK_SCAN, 1024, 0, s2>>>();
    scan2_kernel<<<1, 128, 0, s2>>>();
    scan3_kernel<<<(N_NODES + 255) / 256, 256, 0, s2>>>();
    fill_kernel<<<(N_EDGES + 255) / 256, 256, 0, s2>>>(ew, esrc, edst);
    cudaEventRecord(evB, s2);

    // main: second GEMM half (overlaps agg0 on s3)
    gemm_hmma_kernel<<<ggrid, 256, GEMM_SMEM>>>(128);

    // s3: aggregate cols [0,128) once gemm0 + CSR done
    cudaStreamWaitEvent(s3, evG0, 0);
    cudaStreamWaitEvent(s3, evB, 0);
    aggregate_kernel<<<agg_blocks, 256, 0, s3>>>(bias, out, 0);
    cudaEventRecord(evA0, s3);

    // main: aggregate cols [128,256) after gemm1 + CSR
    cudaStreamWaitEvent(0, evB, 0);
    aggregate_kernel<<<agg_blocks, 256>>>(bias, out, 128);

    // join s3 back into the capture-origin stream
    cudaStreamWaitEvent(0, evA0, 0);
}

// round 15
// speedup vs baseline: 1.0505x; 1.0505x over previous
#include <cuda_runtime.h>
#include <cuda_bf16.h>
#include <cuda_fp16.h>
#include <cstdint>

#define N_NODES 100000
#define N_PAD 100096                 // padded rows for unpredicated A loads
#define N_EDGES 800000
#define IN_SIZE 256
#define OUT_SIZE 256
#define NBLK_SCAN ((N_NODES + 1023) / 1024)   // 98

// ---------------------------------------------------------------------------
// Device scratch
// ---------------------------------------------------------------------------
__device__ __align__(128) __half g_x_h[(size_t)N_PAD * IN_SIZE];          // X fp16 (padded)
__device__ __align__(128) __half g_supp_h[(size_t)N_NODES * OUT_SIZE];    // x @ W (fp16)
__device__ __align__(128) __half g_w_h[IN_SIZE * OUT_SIZE];               // W fp16 [k][n]

__device__ int   g_deg[N_NODES];
__device__ int   g_loc[N_NODES];
__device__ int   g_bsum[128];
__device__ int   g_off[N_NODES + 1];
__device__ int   g_cur[N_NODES];
__device__ __align__(16) uint2 g_edge[N_EDGES];   // {src, weight bits} grouped by dst

// ---------------------------------------------------------------------------
// Helpers
// ---------------------------------------------------------------------------
__device__ __forceinline__ uint32_t smem_u32(const void* p) {
    uint32_t a;
    asm("{ .reg .u64 t; cvta.to.shared.u64 t, %1; cvt.u32.u64 %0, t; }" : "=r"(a) : "l"(p));
    return a;
}
__device__ __forceinline__ void ldsm_x4(uint32_t* r, uint32_t addr) {
    asm volatile("ldmatrix.sync.aligned.m8n8.x4.shared.b16 {%0,%1,%2,%3}, [%4];"
                 : "=r"(r[0]), "=r"(r[1]), "=r"(r[2]), "=r"(r[3]) : "r"(addr));
}
__device__ __forceinline__ void ldsm_x4_t(uint32_t* r, uint32_t addr) {
    asm volatile("ldmatrix.sync.aligned.m8n8.x4.trans.shared.b16 {%0,%1,%2,%3}, [%4];"
                 : "=r"(r[0]), "=r"(r[1]), "=r"(r[2]), "=r"(r[3]) : "r"(addr));
}
__device__ __forceinline__ void mma_f16(float* d, const uint32_t* a, const uint32_t* b) {
    asm volatile(
        "mma.sync.aligned.m16n8k16.row.col.f32.f16.f16.f32 "
        "{%0,%1,%2,%3}, {%4,%5,%6,%7}, {%8,%9}, {%0,%1,%2,%3};"
        : "+f"(d[0]), "+f"(d[1]), "+f"(d[2]), "+f"(d[3])
        : "r"(a[0]), "r"(a[1]), "r"(a[2]), "r"(a[3]), "r"(b[0]), "r"(b[1]));
}
__device__ __forceinline__ uint32_t hpack(float x, float y) {
    __half2 t = __floats2half2_rn(x, y);
    return *reinterpret_cast<uint32_t*>(&t);
}
__device__ __forceinline__ void stcs_f4(float* p, float4 v) {
    asm volatile("st.global.cs.v4.f32 [%0], {%1,%2,%3,%4};"
                 :: "l"(p), "f"(v.x), "f"(v.y), "f"(v.z), "f"(v.w) : "memory");
}
__device__ __forceinline__ void cp16(uint32_t dst, const void* src) {
    asm volatile("cp.async.ca.shared.global [%0], [%1], 16;" :: "r"(dst), "l"(src));
}
#define CP_COMMIT() asm volatile("cp.async.commit_group;" ::: "memory")
#define CP_WAIT(n)  asm volatile("cp.async.wait_group %0;" :: "n"(n) : "memory")

__device__ __forceinline__ float2 h2f2(uint32_t u) {
    __half2 h = *reinterpret_cast<__half2*>(&u);
    return __half22float2(h);
}

// ---------------------------------------------------------------------------
// Prep: X fp32 -> fp16 (padded rows zeroed); W fp32 -> fp16
// ---------------------------------------------------------------------------
__global__ void prep_x_kernel(const float* __restrict__ X) {
    const int idx = blockIdx.x * blockDim.x + threadIdx.x;   // float4 units
    const int total = N_NODES * (IN_SIZE / 4);
    if (idx < total) {
        const float4 f = reinterpret_cast<const float4*>(X)[idx];
        reinterpret_cast<uint2*>(g_x_h)[idx] = make_uint2(hpack(f.x, f.y), hpack(f.z, f.w));
    } else if (idx < N_PAD * (IN_SIZE / 4)) {
        reinterpret_cast<uint2*>(g_x_h)[idx] = make_uint2(0u, 0u);
    }
}

__global__ void prep_w_kernel(const float* __restrict__ W) {
    const int idx = blockIdx.x * blockDim.x + threadIdx.x;
    g_w_h[idx] = __float2half_rn(W[idx]);
}

// ---------------------------------------------------------------------------
// GEMM: supp = Xh @ Wh, fp16 HMMA, all-cp.async 3-stage pipeline.
// CTA 128(M)x256(N), warps 2(M)x4(N) -> warp tile 64x64, KC=32, 1 CTA/SM.
// ---------------------------------------------------------------------------
#define KC 32
#define NCH (IN_SIZE / KC)   // 8
#define LDA 40    // fp16 per A smem row (32 + 8 pad) = 80 B
#define LDB 264   // fp16 per B smem row (256 + 8 pad) = 528 B

#define OFF_A  0
#define OFF_B  10240
#define STAGE  27136          // 10240 + 32*528
#define NSTAGE 3
#define GEMM_SMEM (NSTAGE * STAGE)   // 81408

__global__ __launch_bounds__(256, 1) void gemm_hmma_kernel() {
    extern __shared__ __align__(16) char smem[];
    const uint32_t sb = smem_u32(smem);

    const int tid = threadIdx.x;
    const int lane = tid & 31;
    const int w = tid >> 5;
    const int wm = w & 1;         // 0..1  (M, 64 each)
    const int wn = w >> 1;        // 0..3  (N, 64 each)
    const int tile_m = blockIdx.y * 128;

    float acc[4][8][4];
#pragma unroll
    for (int i = 0; i < 4; i++)
#pragma unroll
        for (int j = 0; j < 8; j++)
#pragma unroll
            for (int q = 0; q < 4; q++) acc[i][j][q] = 0.0f;

    const int lm_row = lane & 15;
    const int lm_coloff = (lane >> 4) * 8;

    // stage issue: all cp.async for chunk `st` into buffer `st % NSTAGE`
    auto issue = [&](int st) {
        const uint32_t buf = sb + (st % NSTAGE) * STAGE;
        const int k0 = st * KC;
        // A: 128 rows x 4 segs of 16B = 512 cp16, 2 per thread
#pragma unroll
        for (int i = 0; i < 2; i++) {
            const int idx = i * 256 + tid;
            const int row = idx >> 2;
            const int seg = idx & 3;
            cp16(buf + OFF_A + row * 80 + seg * 16,
                 &g_x_h[(size_t)(tile_m + row) * IN_SIZE + k0 + seg * 8]);
        }
        // B: 32 rows x 32 segs of 16B = 1024 cp16, 4 per thread
#pragma unroll
        for (int i = 0; i < 4; i++) {
            const int idx = i * 256 + tid;
            const int row = idx >> 5;
            const int seg = idx & 31;
            cp16(buf + OFF_B + row * 528 + seg * 16,
                 &g_w_h[(size_t)(k0 + row) * OUT_SIZE + seg * 8]);
        }
        CP_COMMIT();
    };

    issue(0);
    issue(1);

#pragma unroll
    for (int c = 0; c < NCH; c++) {
        if (c == NCH - 1) { CP_WAIT(0); } else { CP_WAIT(1); }
        __syncthreads();

        if (c + 2 < NCH) issue(c + 2);

        const uint32_t buf = sb + (c % NSTAGE) * STAGE;
        const uint32_t as = buf + OFF_A;
        const uint32_t bs = buf + OFF_B;

#pragma unroll
        for (int kk = 0; kk < 2; kk++) {
            const int ks = kk * 16;
            uint32_t am[4][4];
#pragma unroll
            for (int i = 0; i < 4; i++) {
                const uint32_t off =
                    ((uint32_t)(wm * 64 + i * 16 + lm_row) * LDA + ks + lm_coloff) * 2;
                ldsm_x4(am[i], as + off);
            }
            uint32_t bm[16];
#pragma unroll
            for (int jj = 0; jj < 4; jj++) {
                const uint32_t off =
                    ((uint32_t)(ks + lm_row) * LDB + wn * 64 + jj * 16 + lm_coloff) * 2;
                ldsm_x4_t(&bm[jj * 4], bs + off);
            }
#pragma unroll
            for (int i = 0; i < 4; i++)
#pragma unroll
                for (int j = 0; j < 8; j++)
                    mma_f16(acc[i][j], am[i], &bm[j * 2]);
        }
    }

    // ---- epilogue: fp16 stores
    const int er = lane >> 2;
    const int ec = (lane & 3) * 2;
#pragma unroll
    for (int i = 0; i < 4; i++) {
        const int r0 = tile_m + wm * 64 + i * 16 + er;
#pragma unroll
        for (int j = 0; j < 8; j++) {
            const int col = wn * 64 + j * 8 + ec;
            if (r0 < N_NODES) {
                __half2 h = __floats2half2_rn(acc[i][j][0], acc[i][j][1]);
                *reinterpret_cast<__half2*>(&g_supp_h[(size_t)r0 * OUT_SIZE + col]) = h;
            }
            if (r0 + 8 < N_NODES) {
                __half2 h = __floats2half2_rn(acc[i][j][2], acc[i][j][3]);
                *reinterpret_cast<__half2*>(&g_supp_h[(size_t)(r0 + 8) * OUT_SIZE + col]) = h;
            }
        }
    }
}

// ---------------------------------------------------------------------------
// CSR build: zero -> histogram -> scan(3) -> fill
// ---------------------------------------------------------------------------
__global__ void zero_deg_kernel() {
    const int i = blockIdx.x * blockDim.x + threadIdx.x;
    if (i < N_NODES) g_deg[i] = 0;
}

__global__ void hist_kernel(const int* __restrict__ edst) {
    const int e = blockIdx.x * blockDim.x + threadIdx.x;
    if (e < N_EDGES) atomicAdd(&g_deg[edst[e]], 1);
}

__global__ __launch_bounds__(1024) void scan1_kernel() {
    __shared__ int s[1024];
    const int tid = threadIdx.x;
    const int i = blockIdx.x * 1024 + tid;
    const int v = (i < N_NODES) ? g_deg[i] : 0;
    s[tid] = v;
    __syncthreads();
#pragma unroll
    for (int d = 1; d < 1024; d <<= 1) {
        int t = (tid >= d) ? s[tid - d] : 0;
        __syncthreads();
        s[tid] += t;
        __syncthreads();
    }
    if (i < N_NODES) g_loc[i] = s[tid] - v;
    if (tid == 1023) g_bsum[blockIdx.x] = s[1023];
}

__global__ __launch_bounds__(128) void scan2_kernel() {
    __shared__ int s[128];
    const int tid = threadIdx.x;
    const int v = (tid < NBLK_SCAN) ? g_bsum[tid] : 0;
    s[tid] = v;
    __syncthreads();
#pragma unroll
    for (int d = 1; d < 128; d <<= 1) {
        int t = (tid >= d) ? s[tid - d] : 0;
        __syncthreads();
        s[tid] += t;
        __syncthreads();
    }
    g_bsum[tid] = s[tid] - v;
}

__global__ void scan3_kernel() {
    const int i = blockIdx.x * blockDim.x + threadIdx.x;
    if (i < N_NODES) {
        const int off = g_loc[i] + g_bsum[i >> 10];
        g_off[i] = off;
        g_cur[i] = off;
    }
    if (i == 0) g_off[N_NODES] = N_EDGES;
}

__global__ void fill_kernel(const float* __restrict__ ew,
                            const int* __restrict__ esrc,
                            const int* __restrict__ edst) {
    const int e = blockIdx.x * blockDim.x + threadIdx.x;
    if (e < N_EDGES) {
        const int p = atomicAdd(&g_cur[edst[e]], 1);
        g_edge[p] = make_uint2((uint32_t)esrc[e], __float_as_uint(ew[e]));
    }
}

// ---------------------------------------------------------------------------
// Aggregate: one warp per dst node. out[d] = sum supp_h[src]*w + bias.
// ---------------------------------------------------------------------------
__global__ __launch_bounds__(256) void aggregate_kernel(const float* __restrict__ bias,
                                                        float* __restrict__ out) {
    const int d = (blockIdx.x * blockDim.x + threadIdx.x) >> 5;
    const int lane = threadIdx.x & 31;
    if (d >= N_NODES) return;

    const int beg = g_off[d];
    const int end = g_off[d + 1];

    float4 acc0 = reinterpret_cast<const float4*>(bias)[lane * 2];
    float4 acc1 = reinterpret_cast<const float4*>(bias)[lane * 2 + 1];

    int p = beg;
    for (; p + 1 < end; p += 2) {
        const uint2 e0 = g_edge[p];
        const uint2 e1 = g_edge[p + 1];
        const float w0 = __uint_as_float(e0.y);
        const float w1 = __uint_as_float(e1.y);
        const uint4 v0 = *reinterpret_cast<const uint4*>(
            &g_supp_h[(size_t)e0.x * OUT_SIZE + lane * 8]);
        const uint4 v1 = *reinterpret_cast<const uint4*>(
            &g_supp_h[(size_t)e1.x * OUT_SIZE + lane * 8]);

        float2 f;
        f = h2f2(v0.x); acc0.x = fmaf(f.x, w0, acc0.x); acc0.y = fmaf(f.y, w0, acc0.y);
        f = h2f2(v0.y); acc0.z = fmaf(f.x, w0, acc0.z); acc0.w = fmaf(f.y, w0, acc0.w);
        f = h2f2(v0.z); acc1.x = fmaf(f.x, w0, acc1.x); acc1.y = fmaf(f.y, w0, acc1.y);
        f = h2f2(v0.w); acc1.z = fmaf(f.x, w0, acc1.z); acc1.w = fmaf(f.y, w0, acc1.w);

        f = h2f2(v1.x); acc0.x = fmaf(f.x, w1, acc0.x); acc0.y = fmaf(f.y, w1, acc0.y);
        f = h2f2(v1.y); acc0.z = fmaf(f.x, w1, acc0.z); acc0.w = fmaf(f.y, w1, acc0.w);
        f = h2f2(v1.z); acc1.x = fmaf(f.x, w1, acc1.x); acc1.y = fmaf(f.y, w1, acc1.y);
        f = h2f2(v1.w); acc1.z = fmaf(f.x, w1, acc1.z); acc1.w = fmaf(f.y, w1, acc1.w);
    }
    if (p < end) {
        const uint2 e0 = g_edge[p];
        const float w0 = __uint_as_float(e0.y);
        const uint4 v0 = *reinterpret_cast<const uint4*>(
            &g_supp_h[(size_t)e0.x * OUT_SIZE + lane * 8]);
        float2 f;
        f = h2f2(v0.x); acc0.x = fmaf(f.x, w0, acc0.x); acc0.y = fmaf(f.y, w0, acc0.y);
        f = h2f2(v0.y); acc0.z = fmaf(f.x, w0, acc0.z); acc0.w = fmaf(f.y, w0, acc0.w);
        f = h2f2(v0.z); acc1.x = fmaf(f.x, w0, acc1.x); acc1.y = fmaf(f.y, w0, acc1.y);
        f = h2f2(v0.w); acc1.z = fmaf(f.x, w0, acc1.z); acc1.w = fmaf(f.y, w0, acc1.w);
    }

    float* op = &out[(size_t)d * OUT_SIZE + lane * 8];
    stcs_f4(op, acc0);
    stcs_f4(op + 4, acc1);
}

// ---------------------------------------------------------------------------
extern "C" void kernel_launch(void* const* d_in, const int* in_sizes, int n_in,
                              void* d_out, int out_size) {
    const float* x      = (const float*)d_in[0];
    const float* weight = (const float*)d_in[1];
    const float* bias   = (const float*)d_in[2];
    const float* ew     = (const float*)d_in[3];
    const int*   esrc   = (const int*)d_in[4];
    const int*   edst   = (const int*)d_in[5];
    float* out = (float*)d_out;

    static cudaStream_t s2 = nullptr;
    static cudaEvent_t evA = nullptr, evB = nullptr;
    if (!s2) {
        cudaStreamCreateWithFlags(&s2, cudaStreamNonBlocking);
        cudaEventCreateWithFlags(&evA, cudaEventDisableTiming);
        cudaEventCreateWithFlags(&evB, cudaEventDisableTiming);
        cudaFuncSetAttribute(gemm_hmma_kernel, cudaFuncAttributeMaxDynamicSharedMemorySize,
                             GEMM_SMEM);
    }

    cudaEventRecord(evA, 0);
    cudaStreamWaitEvent(s2, evA, 0);

    // Launch order chosen so gemm is the 4th launch (profiled by harness ncu).
    prep_x_kernel<<<(N_PAD * (IN_SIZE / 4) + 255) / 256, 256>>>(x);         // 0 (main)
    prep_w_kernel<<<IN_SIZE * OUT_SIZE / 256, 256>>>(weight);               // 1 (main)
    zero_deg_kernel<<<(N_NODES + 255) / 256, 256, 0, s2>>>();               // 2 (s2)
    dim3 ggrid(1, (N_NODES + 127) / 128);
    gemm_hmma_kernel<<<ggrid, 256, GEMM_SMEM>>>();                          // 3 (main)

    hist_kernel<<<(N_EDGES + 255) / 256, 256, 0, s2>>>(edst);               // 4 (s2)
    scan1_kernel<<<NBLK_SCAN, 1024, 0, s2>>>();
    scan2_kernel<<<1, 128, 0, s2>>>();
    scan3_kernel<<<(N_NODES + 255) / 256, 256, 0, s2>>>();
    fill_kernel<<<(N_EDGES + 255) / 256, 256, 0, s2>>>(ew, esrc, edst);
    cudaEventRecord(evB, s2);

    cudaStreamWaitEvent(0, evB, 0);
    aggregate_kernel<<<(N_NODES * 32 + 255) / 256, 256>>>(bias, out);
}

// round 16
// speedup vs baseline: 1.1084x; 1.0551x over previous
#include <cuda_runtime.h>
#include <cuda_bf16.h>
#include <cuda_fp16.h>
#include <cstdint>

#define N_NODES 100000
#define N_PAD 100096                 // padded rows for unpredicated A loads
#define N_EDGES 800000
#define IN_SIZE 256
#define OUT_SIZE 256
#define NBLK_SCAN ((N_NODES + 1023) / 1024)   // 98
#define M_SPLIT 50048                // first-half rows (391 tiles of 128)

// ---------------------------------------------------------------------------
// Device scratch
// ---------------------------------------------------------------------------
__device__ __align__(128) __half g_x_h[(size_t)N_PAD * IN_SIZE];          // X fp16 (padded)
__device__ __align__(128) __half g_supp_h[(size_t)N_NODES * OUT_SIZE];    // x @ W (fp16)
__device__ __align__(128) __half g_w_h[IN_SIZE * OUT_SIZE];               // W fp16 [k][n]

__device__ int   g_deg[N_NODES];
__device__ int   g_loc[N_NODES];
__device__ int   g_bsum[128];
__device__ int   g_off[N_NODES + 1];
__device__ int   g_cur[N_NODES];
__device__ __align__(16) uint2 g_edge[N_EDGES];   // {src, weight bits} grouped by dst

// ---------------------------------------------------------------------------
// Helpers
// ---------------------------------------------------------------------------
__device__ __forceinline__ uint32_t smem_u32(const void* p) {
    uint32_t a;
    asm("{ .reg .u64 t; cvta.to.shared.u64 t, %1; cvt.u32.u64 %0, t; }" : "=r"(a) : "l"(p));
    return a;
}
__device__ __forceinline__ void ldsm_x4(uint32_t* r, uint32_t addr) {
    asm volatile("ldmatrix.sync.aligned.m8n8.x4.shared.b16 {%0,%1,%2,%3}, [%4];"
                 : "=r"(r[0]), "=r"(r[1]), "=r"(r[2]), "=r"(r[3]) : "r"(addr));
}
__device__ __forceinline__ void ldsm_x4_t(uint32_t* r, uint32_t addr) {
    asm volatile("ldmatrix.sync.aligned.m8n8.x4.trans.shared.b16 {%0,%1,%2,%3}, [%4];"
                 : "=r"(r[0]), "=r"(r[1]), "=r"(r[2]), "=r"(r[3]) : "r"(addr));
}
__device__ __forceinline__ void mma_f16(float* d, const uint32_t* a, const uint32_t* b) {
    asm volatile(
        "mma.sync.aligned.m16n8k16.row.col.f32.f16.f16.f32 "
        "{%0,%1,%2,%3}, {%4,%5,%6,%7}, {%8,%9}, {%0,%1,%2,%3};"
        : "+f"(d[0]), "+f"(d[1]), "+f"(d[2]), "+f"(d[3])
        : "r"(a[0]), "r"(a[1]), "r"(a[2]), "r"(a[3]), "r"(b[0]), "r"(b[1]));
}
__device__ __forceinline__ uint32_t hpack(float x, float y) {
    __half2 t = __floats2half2_rn(x, y);
    return *reinterpret_cast<uint32_t*>(&t);
}
__device__ __forceinline__ void stcs_f4(float* p, float4 v) {
    asm volatile("st.global.cs.v4.f32 [%0], {%1,%2,%3,%4};"
                 :: "l"(p), "f"(v.x), "f"(v.y), "f"(v.z), "f"(v.w) : "memory");
}
__device__ __forceinline__ void cp16(uint32_t dst, const void* src) {
    asm volatile("cp.async.ca.shared.global [%0], [%1], 16;" :: "r"(dst), "l"(src));
}
#define CP_COMMIT() asm volatile("cp.async.commit_group;" ::: "memory")
#define CP_WAIT(n)  asm volatile("cp.async.wait_group %0;" :: "n"(n) : "memory")

__device__ __forceinline__ float2 h2f2(uint32_t u) {
    __half2 h = *reinterpret_cast<__half2*>(&u);
    return __half22float2(h);
}

// ---------------------------------------------------------------------------
// Prep: X fp32 -> fp16 over an index range (float4 units); pad rows zeroed.
// ---------------------------------------------------------------------------
__global__ void prep_x_kernel(const float* __restrict__ X, int base) {
    const int idx = base + blockIdx.x * blockDim.x + threadIdx.x;   // float4 units
    const int total = N_NODES * (IN_SIZE / 4);
    if (idx < total) {
        const float4 f = reinterpret_cast<const float4*>(X)[idx];
        reinterpret_cast<uint2*>(g_x_h)[idx] = make_uint2(hpack(f.x, f.y), hpack(f.z, f.w));
    } else if (idx < N_PAD * (IN_SIZE / 4)) {
        reinterpret_cast<uint2*>(g_x_h)[idx] = make_uint2(0u, 0u);
    }
}

__global__ void prep_w_kernel(const float* __restrict__ W) {
    const int idx = blockIdx.x * blockDim.x + threadIdx.x;
    g_w_h[idx] = __float2half_rn(W[idx]);
}

// ---------------------------------------------------------------------------
// GEMM slice: supp[m_base:...] = Xh @ Wh, fp16 HMMA, all-cp.async 3-stage.
// CTA 128(M)x128(N), warps 4(M)x2(N) -> warp tile 32x64, KC=32, 2 CTAs/SM.
// ---------------------------------------------------------------------------
#define KC 32
#define NCH (IN_SIZE / KC)   // 8
#define LDA 40    // fp16 per A smem row (32 + 8 pad) = 80 B
#define LDB 136   // fp16 per B smem row (128 + 8 pad) = 272 B

#define OFF_A  0
#define OFF_B  10240
#define STAGE  18944          // 10240 + 32*272
#define NSTAGE 3
#define GEMM_SMEM (NSTAGE * STAGE)   // 56832

__global__ __launch_bounds__(256, 2) void gemm_hmma_kernel(int m_base) {
    extern __shared__ __align__(16) char smem[];
    const uint32_t sb = smem_u32(smem);

    const int tid = threadIdx.x;
    const int lane = tid & 31;
    const int w = tid >> 5;
    const int wm = w >> 1;        // 0..3  (M)
    const int wn = w & 1;         // 0..1  (N)
    const int tile_n = blockIdx.x * 128;
    const int tile_m = m_base + blockIdx.y * 128;

    float acc[2][8][4];
#pragma unroll
    for (int i = 0; i < 2; i++)
#pragma unroll
        for (int j = 0; j < 8; j++)
#pragma unroll
            for (int q = 0; q < 4; q++) acc[i][j][q] = 0.0f;

    const int lm_row = lane & 15;
    const int lm_coloff = (lane >> 4) * 8;

    auto issue = [&](int st) {
        const uint32_t buf = sb + (st % NSTAGE) * STAGE;
        const int k0 = st * KC;
        // A: 128 rows x 4 segs of 16B = 512 cp16, 2 per thread
#pragma unroll
        for (int i = 0; i < 2; i++) {
            const int idx = i * 256 + tid;
            const int row = idx >> 2;
            const int seg = idx & 3;
            cp16(buf + OFF_A + row * 80 + seg * 16,
                 &g_x_h[(size_t)(tile_m + row) * IN_SIZE + k0 + seg * 8]);
        }
        // B: 32 rows x 16 segs of 16B = 512 cp16, 2 per thread
#pragma unroll
        for (int i = 0; i < 2; i++) {
            const int idx = i * 256 + tid;
            const int row = idx >> 4;
            const int seg = idx & 15;
            cp16(buf + OFF_B + row * 272 + seg * 16,
                 &g_w_h[(size_t)(k0 + row) * OUT_SIZE + tile_n + seg * 8]);
        }
        CP_COMMIT();
    };

    issue(0);
    issue(1);

#pragma unroll
    for (int c = 0; c < NCH; c++) {
        if (c == NCH - 1) { CP_WAIT(0); } else { CP_WAIT(1); }
        __syncthreads();

        if (c + 2 < NCH) issue(c + 2);

        const uint32_t buf = sb + (c % NSTAGE) * STAGE;
        const uint32_t as = buf + OFF_A;
        const uint32_t bs = buf + OFF_B;

#pragma unroll
        for (int kk = 0; kk < 2; kk++) {
            const int ks = kk * 16;
            uint32_t am[2][4];
#pragma unroll
            for (int i = 0; i < 2; i++) {
                const uint32_t off =
                    ((uint32_t)(wm * 32 + i * 16 + lm_row) * LDA + ks + lm_coloff) * 2;
                ldsm_x4(am[i], as + off);
            }
            uint32_t bm[16];
#pragma unroll
            for (int jj = 0; jj < 4; jj++) {
                const uint32_t off =
                    ((uint32_t)(ks + lm_row) * LDB + wn * 64 + jj * 16 + lm_coloff) * 2;
                ldsm_x4_t(&bm[jj * 4], bs + off);
            }
#pragma unroll
            for (int i = 0; i < 2; i++)
#pragma unroll
                for (int j = 0; j < 8; j++)
                    mma_f16(acc[i][j], am[i], &bm[j * 2]);
        }
    }

    // ---- epilogue: fp16 stores
    const int er = lane >> 2;
    const int ec = (lane & 3) * 2;
#pragma unroll
    for (int i = 0; i < 2; i++) {
        const int r0 = tile_m + wm * 32 + i * 16 + er;
#pragma unroll
        for (int j = 0; j < 8; j++) {
            const int col = tile_n + wn * 64 + j * 8 + ec;
            if (r0 < N_NODES) {
                __half2 h = __floats2half2_rn(acc[i][j][0], acc[i][j][1]);
                *reinterpret_cast<__half2*>(&g_supp_h[(size_t)r0 * OUT_SIZE + col]) = h;
            }
            if (r0 + 8 < N_NODES) {
                __half2 h = __floats2half2_rn(acc[i][j][2], acc[i][j][3]);
                *reinterpret_cast<__half2*>(&g_supp_h[(size_t)(r0 + 8) * OUT_SIZE + col]) = h;
            }
        }
    }
}

// ---------------------------------------------------------------------------
// CSR build: zero -> histogram -> scan(3) -> fill
// ---------------------------------------------------------------------------
__global__ void zero_deg_kernel() {
    const int i = blockIdx.x * blockDim.x + threadIdx.x;
    if (i < N_NODES) g_deg[i] = 0;
}

__global__ void hist_kernel(const int* __restrict__ edst) {
    const int e = blockIdx.x * blockDim.x + threadIdx.x;
    if (e < N_EDGES) atomicAdd(&g_deg[edst[e]], 1);
}

__global__ __launch_bounds__(1024) void scan1_kernel() {
    __shared__ int s[1024];
    const int tid = threadIdx.x;
    const int i = blockIdx.x * 1024 + tid;
    const int v = (i < N_NODES) ? g_deg[i] : 0;
    s[tid] = v;
    __syncthreads();
#pragma unroll
    for (int d = 1; d < 1024; d <<= 1) {
        int t = (tid >= d) ? s[tid - d] : 0;
        __syncthreads();
        s[tid] += t;
        __syncthreads();
    }
    if (i < N_NODES) g_loc[i] = s[tid] - v;
    if (tid == 1023) g_bsum[blockIdx.x] = s[1023];
}

__global__ __launch_bounds__(128) void scan2_kernel() {
    __shared__ int s[128];
    const int tid = threadIdx.x;
    const int v = (tid < NBLK_SCAN) ? g_bsum[tid] : 0;
    s[tid] = v;
    __syncthreads();
#pragma unroll
    for (int d = 1; d < 128; d <<= 1) {
        int t = (tid >= d) ? s[tid - d] : 0;
        __syncthreads();
        s[tid] += t;
        __syncthreads();
    }
    g_bsum[tid] = s[tid] - v;
}

__global__ void scan3_kernel() {
    const int i = blockIdx.x * blockDim.x + threadIdx.x;
    if (i < N_NODES) {
        const int off = g_loc[i] + g_bsum[i >> 10];
        g_off[i] = off;
        g_cur[i] = off;
    }
    if (i == 0) g_off[N_NODES] = N_EDGES;
}

__global__ void fill_kernel(const float* __restrict__ ew,
                            const int* __restrict__ esrc,
                            const int* __restrict__ edst) {
    const int e = blockIdx.x * blockDim.x + threadIdx.x;
    if (e < N_EDGES) {
        const int p = atomicAdd(&g_cur[edst[e]], 1);
        g_edge[p] = make_uint2((uint32_t)esrc[e], __float_as_uint(ew[e]));
    }
}

// ---------------------------------------------------------------------------
// Aggregate: one warp per dst node. out[d] = sum supp_h[src]*w + bias.
// ---------------------------------------------------------------------------
__global__ __launch_bounds__(256) void aggregate_kernel(const float* __restrict__ bias,
                                                        float* __restrict__ out) {
    const int d = (blockIdx.x * blockDim.x + threadIdx.x) >> 5;
    const int lane = threadIdx.x & 31;
    if (d >= N_NODES) return;

    const int beg = g_off[d];
    const int end = g_off[d + 1];

    float4 acc0 = reinterpret_cast<const float4*>(bias)[lane * 2];
    float4 acc1 = reinterpret_cast<const float4*>(bias)[lane * 2 + 1];

    int p = beg;
    for (; p + 1 < end; p += 2) {
        const uint2 e0 = g_edge[p];
        const uint2 e1 = g_edge[p + 1];
        const float w0 = __uint_as_float(e0.y);
        const float w1 = __uint_as_float(e1.y);
        const uint4 v0 = *reinterpret_cast<const uint4*>(
            &g_supp_h[(size_t)e0.x * OUT_SIZE + lane * 8]);
        const uint4 v1 = *reinterpret_cast<const uint4*>(
            &g_supp_h[(size_t)e1.x * OUT_SIZE + lane * 8]);

        float2 f;
        f = h2f2(v0.x); acc0.x = fmaf(f.x, w0, acc0.x); acc0.y = fmaf(f.y, w0, acc0.y);
        f = h2f2(v0.y); acc0.z = fmaf(f.x, w0, acc0.z); acc0.w = fmaf(f.y, w0, acc0.w);
        f = h2f2(v0.z); acc1.x = fmaf(f.x, w0, acc1.x); acc1.y = fmaf(f.y, w0, acc1.y);
        f = h2f2(v0.w); acc1.z = fmaf(f.x, w0, acc1.z); acc1.w = fmaf(f.y, w0, acc1.w);

        f = h2f2(v1.x); acc0.x = fmaf(f.x, w1, acc0.x); acc0.y = fmaf(f.y, w1, acc0.y);
        f = h2f2(v1.y); acc0.z = fmaf(f.x, w1, acc0.z); acc0.w = fmaf(f.y, w1, acc0.w);
        f = h2f2(v1.z); acc1.x = fmaf(f.x, w1, acc1.x); acc1.y = fmaf(f.y, w1, acc1.y);
        f = h2f2(v1.w); acc1.z = fmaf(f.x, w1, acc1.z); acc1.w = fmaf(f.y, w1, acc1.w);
    }
    if (p < end) {
        const uint2 e0 = g_edge[p];
        const float w0 = __uint_as_float(e0.y);
        const uint4 v0 = *reinterpret_cast<const uint4*>(
            &g_supp_h[(size_t)e0.x * OUT_SIZE + lane * 8]);
        float2 f;
        f = h2f2(v0.x); acc0.x = fmaf(f.x, w0, acc0.x); acc0.y = fmaf(f.y, w0, acc0.y);
        f = h2f2(v0.y); acc0.z = fmaf(f.x, w0, acc0.z); acc0.w = fmaf(f.y, w0, acc0.w);
        f = h2f2(v0.z); acc1.x = fmaf(f.x, w0, acc1.x); acc1.y = fmaf(f.y, w0, acc1.y);
        f = h2f2(v0.w); acc1.z = fmaf(f.x, w0, acc1.z); acc1.w = fmaf(f.y, w0, acc1.w);
    }

    float* op = &out[(size_t)d * OUT_SIZE + lane * 8];
    stcs_f4(op, acc0);
    stcs_f4(op + 4, acc1);
}

// ---------------------------------------------------------------------------
extern "C" void kernel_launch(void* const* d_in, const int* in_sizes, int n_in,
                              void* d_out, int out_size) {
    const float* x      = (const float*)d_in[0];
    const float* weight = (const float*)d_in[1];
    const float* bias   = (const float*)d_in[2];
    const float* ew     = (const float*)d_in[3];
    const int*   esrc   = (const int*)d_in[4];
    const int*   edst   = (const int*)d_in[5];
    float* out = (float*)d_out;

    static cudaStream_t s2 = nullptr, s3 = nullptr;
    static cudaEvent_t evA = nullptr, evB = nullptr, evW = nullptr, evP0 = nullptr, evG1 = nullptr;
    if (!s2) {
        cudaStreamCreateWithFlags(&s2, cudaStreamNonBlocking);
        cudaStreamCreateWithFlags(&s3, cudaStreamNonBlocking);
        cudaEventCreateWithFlags(&evA, cudaEventDisableTiming);
        cudaEventCreateWithFlags(&evB, cudaEventDisableTiming);
        cudaEventCreateWithFlags(&evW, cudaEventDisableTiming);
        cudaEventCreateWithFlags(&evP0, cudaEventDisableTiming);
        cudaEventCreateWithFlags(&evG1, cudaEventDisableTiming);
        cudaFuncSetAttribute(gemm_hmma_kernel, cudaFuncAttributeMaxDynamicSharedMemorySize,
                             GEMM_SMEM);
    }

    cudaEventRecord(evA, 0);
    cudaStreamWaitEvent(s2, evA, 0);
    cudaStreamWaitEvent(s3, evA, 0);

    const int H0_F4 = M_SPLIT * (IN_SIZE / 4);            // 50048*64
    const int H1_F4 = (N_PAD - M_SPLIT) * (IN_SIZE / 4);  // 50048*64

    // 1) main: prep X rows [0, M_SPLIT)
    prep_x_kernel<<<H0_F4 / 256, 256>>>(x, 0);
    cudaEventRecord(evP0, 0);

    // 2-3) s2: prep W, zero deg
    prep_w_kernel<<<IN_SIZE * OUT_SIZE / 256, 256, 0, s2>>>(weight);
    cudaEventRecord(evW, s2);
    zero_deg_kernel<<<(N_NODES + 255) / 256, 256, 0, s2>>>();

    // 4) main: gemm half 0 (profiled slot)
    cudaStreamWaitEvent(0, evW, 0);
    dim3 ggrid(OUT_SIZE / 128, M_SPLIT / 128);            // (2, 391)
    gemm_hmma_kernel<<<ggrid, 256, GEMM_SMEM>>>(0);

    // 5-6) s3: prep X rows [M_SPLIT, N_PAD) overlapping gemm0, then gemm half 1
    cudaStreamWaitEvent(s3, evP0, 0);
    cudaStreamWaitEvent(s3, evW, 0);
    prep_x_kernel<<<H1_F4 / 256, 256, 0, s3>>>(x, H0_F4);
    gemm_hmma_kernel<<<ggrid, 256, GEMM_SMEM, s3>>>(M_SPLIT);
    cudaEventRecord(evG1, s3);

    // s2: rest of CSR build
    hist_kernel<<<(N_EDGES + 255) / 256, 256, 0, s2>>>(edst);
    scan1_kernel<<<NBLK_SCAN, 1024, 0, s2>>>();
    scan2_kernel<<<1, 128, 0, s2>>>();
    scan3_kernel<<<(N_NODES + 255) / 256, 256, 0, s2>>>();
    fill_kernel<<<(N_EDGES + 255) / 256, 256, 0, s2>>>(ew, esrc, edst);
    cudaEventRecord(evB, s2);

    // main: aggregate after gemm0 (in-stream), gemm1 (evG1), CSR (evB)
    cudaStreamWaitEvent(0, evB, 0);
    cudaStreamWaitEvent(0, evG1, 0);
    aggregate_kernel<<<(N_NODES * 32 + 255) / 256, 256>>>(bias, out);
}

// round 17
// speedup vs baseline: 1.1285x; 1.0182x over previous
#include <cuda_runtime.h>
#include <cuda_bf16.h>
#include <cuda_fp16.h>
#include <cstdint>

#define N_NODES 100000
#define N_PAD 100096                 // padded rows for unpredicated A loads
#define N_EDGES 800000
#define IN_SIZE 256
#define OUT_SIZE 256
#define NBLK_SCAN ((N_NODES + 1023) / 1024)   // 98

// M slices: 196/196/196/194 tiles of 128 rows
#define S0_ROWS 25088
#define S1_ROWS 25088
#define S2_ROWS 25088
#define S3_ROWS 24832
#define S0_F4 (S0_ROWS * 64)         // 1605632
#define S1_F4 (S1_ROWS * 64)
#define S2_F4 (S2_ROWS * 64)
#define S3_F4 (S3_ROWS * 64)         // 1589248 (covers pad rows)
#define W_F4 (IN_SIZE * OUT_SIZE / 4) // 16384

// ---------------------------------------------------------------------------
// Device scratch
// ---------------------------------------------------------------------------
__device__ __align__(128) __half g_x_h[(size_t)N_PAD * IN_SIZE];          // X fp16 (padded)
__device__ __align__(128) __half g_supp_h[(size_t)N_NODES * OUT_SIZE];    // x @ W (fp16)
__device__ __align__(128) __half g_w_h[IN_SIZE * OUT_SIZE];               // W fp16 [k][n]

__device__ int   g_deg[N_NODES];
__device__ int   g_loc[N_NODES];
__device__ int   g_bsum[128];
__device__ int   g_off[N_NODES + 1];
__device__ int   g_cur[N_NODES];
__device__ __align__(16) uint2 g_edge[N_EDGES];   // {src, weight bits} grouped by dst

// ---------------------------------------------------------------------------
// Helpers
// ---------------------------------------------------------------------------
__device__ __forceinline__ uint32_t smem_u32(const void* p) {
    uint32_t a;
    asm("{ .reg .u64 t; cvta.to.shared.u64 t, %1; cvt.u32.u64 %0, t; }" : "=r"(a) : "l"(p));
    return a;
}
__device__ __forceinline__ void ldsm_x4(uint32_t* r, uint32_t addr) {
    asm volatile("ldmatrix.sync.aligned.m8n8.x4.shared.b16 {%0,%1,%2,%3}, [%4];"
                 : "=r"(r[0]), "=r"(r[1]), "=r"(r[2]), "=r"(r[3]) : "r"(addr));
}
__device__ __forceinline__ void ldsm_x4_t(uint32_t* r, uint32_t addr) {
    asm volatile("ldmatrix.sync.aligned.m8n8.x4.trans.shared.b16 {%0,%1,%2,%3}, [%4];"
                 : "=r"(r[0]), "=r"(r[1]), "=r"(r[2]), "=r"(r[3]) : "r"(addr));
}
__device__ __forceinline__ void mma_f16(float* d, const uint32_t* a, const uint32_t* b) {
    asm volatile(
        "mma.sync.aligned.m16n8k16.row.col.f32.f16.f16.f32 "
        "{%0,%1,%2,%3}, {%4,%5,%6,%7}, {%8,%9}, {%0,%1,%2,%3};"
        : "+f"(d[0]), "+f"(d[1]), "+f"(d[2]), "+f"(d[3])
        : "r"(a[0]), "r"(a[1]), "r"(a[2]), "r"(a[3]), "r"(b[0]), "r"(b[1]));
}
__device__ __forceinline__ uint32_t hpack(float x, float y) {
    __half2 t = __floats2half2_rn(x, y);
    return *reinterpret_cast<uint32_t*>(&t);
}
__device__ __forceinline__ void stcs_f4(float* p, float4 v) {
    asm volatile("st.global.cs.v4.f32 [%0], {%1,%2,%3,%4};"
                 :: "l"(p), "f"(v.x), "f"(v.y), "f"(v.z), "f"(v.w) : "memory");
}
__device__ __forceinline__ void cp16(uint32_t dst, const void* src) {
    asm volatile("cp.async.ca.shared.global [%0], [%1], 16;" :: "r"(dst), "l"(src));
}
#define CP_COMMIT() asm volatile("cp.async.commit_group;" ::: "memory")
#define CP_WAIT(n)  asm volatile("cp.async.wait_group %0;" :: "n"(n) : "memory")

__device__ __forceinline__ float2 h2f2(uint32_t u) {
    __half2 h = *reinterpret_cast<__half2*>(&u);
    return __half22float2(h);
}

// ---------------------------------------------------------------------------
// Prep kernels
// ---------------------------------------------------------------------------
// Slice 0 + W fused: idx < S0_F4 -> X conversion; else -> W conversion.
__global__ void prep_xw_kernel(const float* __restrict__ X, const float* __restrict__ W) {
    const int idx = blockIdx.x * blockDim.x + threadIdx.x;
    if (idx < S0_F4) {
        const float4 f = reinterpret_cast<const float4*>(X)[idx];
        reinterpret_cast<uint2*>(g_x_h)[idx] = make_uint2(hpack(f.x, f.y), hpack(f.z, f.w));
    } else {
        const int wi = idx - S0_F4;
        if (wi < W_F4) {
            const float4 f = reinterpret_cast<const float4*>(W)[wi];
            reinterpret_cast<uint2*>(g_w_h)[wi] = make_uint2(hpack(f.x, f.y), hpack(f.z, f.w));
        }
    }
}

// X fp32 -> fp16 over [base, base+count) f4 units; pad rows zeroed.
__global__ void prep_x_kernel(const float* __restrict__ X, int base) {
    const int idx = base + blockIdx.x * blockDim.x + threadIdx.x;
    const int total = N_NODES * (IN_SIZE / 4);
    if (idx < total) {
        const float4 f = reinterpret_cast<const float4*>(X)[idx];
        reinterpret_cast<uint2*>(g_x_h)[idx] = make_uint2(hpack(f.x, f.y), hpack(f.z, f.w));
    } else if (idx < N_PAD * (IN_SIZE / 4)) {
        reinterpret_cast<uint2*>(g_x_h)[idx] = make_uint2(0u, 0u);
    }
}

// ---------------------------------------------------------------------------
// GEMM slice: supp[m_base:...] = Xh @ Wh, fp16 HMMA, all-cp.async 3-stage.
// CTA 128(M)x128(N), warps 4(M)x2(N) -> warp tile 32x64, KC=32, 2 CTAs/SM.
// ---------------------------------------------------------------------------
#define KC 32
#define NCH (IN_SIZE / KC)   // 8
#define LDA 40    // fp16 per A smem row (32 + 8 pad) = 80 B
#define LDB 136   // fp16 per B smem row (128 + 8 pad) = 272 B

#define OFF_A  0
#define OFF_B  10240
#define STAGE  18944          // 10240 + 32*272
#define NSTAGE 3
#define GEMM_SMEM (NSTAGE * STAGE)   // 56832

__global__ __launch_bounds__(256, 2) void gemm_hmma_kernel(int m_base) {
    extern __shared__ __align__(16) char smem[];
    const uint32_t sb = smem_u32(smem);

    const int tid = threadIdx.x;
    const int lane = tid & 31;
    const int w = tid >> 5;
    const int wm = w >> 1;        // 0..3  (M)
    const int wn = w & 1;         // 0..1  (N)
    const int tile_n = blockIdx.x * 128;
    const int tile_m = m_base + blockIdx.y * 128;

    float acc[2][8][4];
#pragma unroll
    for (int i = 0; i < 2; i++)
#pragma unroll
        for (int j = 0; j < 8; j++)
#pragma unroll
            for (int q = 0; q < 4; q++) acc[i][j][q] = 0.0f;

    const int lm_row = lane & 15;
    const int lm_coloff = (lane >> 4) * 8;

    auto issue = [&](int st) {
        const uint32_t buf = sb + (st % NSTAGE) * STAGE;
        const int k0 = st * KC;
#pragma unroll
        for (int i = 0; i < 2; i++) {
            const int idx = i * 256 + tid;
            const int row = idx >> 2;
            const int seg = idx & 3;
            cp16(buf + OFF_A + row * 80 + seg * 16,
                 &g_x_h[(size_t)(tile_m + row) * IN_SIZE + k0 + seg * 8]);
        }
#pragma unroll
        for (int i = 0; i < 2; i++) {
            const int idx = i * 256 + tid;
            const int row = idx >> 4;
            const int seg = idx & 15;
            cp16(buf + OFF_B + row * 272 + seg * 16,
                 &g_w_h[(size_t)(k0 + row) * OUT_SIZE + tile_n + seg * 8]);
        }
        CP_COMMIT();
    };

    issue(0);
    issue(1);

#pragma unroll
    for (int c = 0; c < NCH; c++) {
        if (c == NCH - 1) { CP_WAIT(0); } else { CP_WAIT(1); }
        __syncthreads();

        if (c + 2 < NCH) issue(c + 2);

        const uint32_t buf = sb + (c % NSTAGE) * STAGE;
        const uint32_t as = buf + OFF_A;
        const uint32_t bs = buf + OFF_B;

#pragma unroll
        for (int kk = 0; kk < 2; kk++) {
            const int ks = kk * 16;
            uint32_t am[2][4];
#pragma unroll
            for (int i = 0; i < 2; i++) {
                const uint32_t off =
                    ((uint32_t)(wm * 32 + i * 16 + lm_row) * LDA + ks + lm_coloff) * 2;
                ldsm_x4(am[i], as + off);
            }
            uint32_t bm[16];
#pragma unroll
            for (int jj = 0; jj < 4; jj++) {
                const uint32_t off =
                    ((uint32_t)(ks + lm_row) * LDB + wn * 64 + jj * 16 + lm_coloff) * 2;
                ldsm_x4_t(&bm[jj * 4], bs + off);
            }
#pragma unroll
            for (int i = 0; i < 2; i++)
#pragma unroll
                for (int j = 0; j < 8; j++)
                    mma_f16(acc[i][j], am[i], &bm[j * 2]);
        }
    }

    // ---- epilogue: fp16 stores
    const int er = lane >> 2;
    const int ec = (lane & 3) * 2;
#pragma unroll
    for (int i = 0; i < 2; i++) {
        const int r0 = tile_m + wm * 32 + i * 16 + er;
#pragma unroll
        for (int j = 0; j < 8; j++) {
            const int col = tile_n + wn * 64 + j * 8 + ec;
            if (r0 < N_NODES) {
                __half2 h = __floats2half2_rn(acc[i][j][0], acc[i][j][1]);
                *reinterpret_cast<__half2*>(&g_supp_h[(size_t)r0 * OUT_SIZE + col]) = h;
            }
            if (r0 + 8 < N_NODES) {
                __half2 h = __floats2half2_rn(acc[i][j][2], acc[i][j][3]);
                *reinterpret_cast<__half2*>(&g_supp_h[(size_t)(r0 + 8) * OUT_SIZE + col]) = h;
            }
        }
    }
}

// ---------------------------------------------------------------------------
// CSR build: zero -> histogram -> scan(3) -> fill
// ---------------------------------------------------------------------------
__global__ void zero_deg_kernel() {
    const int i = blockIdx.x * blockDim.x + threadIdx.x;
    if (i < N_NODES) g_deg[i] = 0;
}

__global__ void hist_kernel(const int* __restrict__ edst) {
    const int e = blockIdx.x * blockDim.x + threadIdx.x;
    if (e < N_EDGES) atomicAdd(&g_deg[edst[e]], 1);
}

__global__ __launch_bounds__(1024) void scan1_kernel() {
    __shared__ int s[1024];
    const int tid = threadIdx.x;
    const int i = blockIdx.x * 1024 + tid;
    const int v = (i < N_NODES) ? g_deg[i] : 0;
    s[tid] = v;
    __syncthreads();
#pragma unroll
    for (int d = 1; d < 1024; d <<= 1) {
        int t = (tid >= d) ? s[tid - d] : 0;
        __syncthreads();
        s[tid] += t;
        __syncthreads();
    }
    if (i < N_NODES) g_loc[i] = s[tid] - v;
    if (tid == 1023) g_bsum[blockIdx.x] = s[1023];
}

__global__ __launch_bounds__(128) void scan2_kernel() {
    __shared__ int s[128];
    const int tid = threadIdx.x;
    const int v = (tid < NBLK_SCAN) ? g_bsum[tid] : 0;
    s[tid] = v;
    __syncthreads();
#pragma unroll
    for (int d = 1; d < 128; d <<= 1) {
        int t = (tid >= d) ? s[tid - d] : 0;
        __syncthreads();
        s[tid] += t;
        __syncthreads();
    }
    g_bsum[tid] = s[tid] - v;
}

__global__ void scan3_kernel() {
    const int i = blockIdx.x * blockDim.x + threadIdx.x;
    if (i < N_NODES) {
        const int off = g_loc[i] + g_bsum[i >> 10];
        g_off[i] = off;
        g_cur[i] = off;
    }
    if (i == 0) g_off[N_NODES] = N_EDGES;
}

__global__ void fill_kernel(const float* __restrict__ ew,
                            const int* __restrict__ esrc,
                            const int* __restrict__ edst) {
    const int e = blockIdx.x * blockDim.x + threadIdx.x;
    if (e < N_EDGES) {
        const int p = atomicAdd(&g_cur[edst[e]], 1);
        g_edge[p] = make_uint2((uint32_t)esrc[e], __float_as_uint(ew[e]));
    }
}

// ---------------------------------------------------------------------------
// Aggregate: one warp per dst node. out[d] = sum supp_h[src]*w + bias.
// ---------------------------------------------------------------------------
__global__ __launch_bounds__(256) void aggregate_kernel(const float* __restrict__ bias,
                                                        float* __restrict__ out) {
    const int d = (blockIdx.x * blockDim.x + threadIdx.x) >> 5;
    const int lane = threadIdx.x & 31;
    if (d >= N_NODES) return;

    const int beg = g_off[d];
    const int end = g_off[d + 1];

    float4 acc0 = reinterpret_cast<const float4*>(bias)[lane * 2];
    float4 acc1 = reinterpret_cast<const float4*>(bias)[lane * 2 + 1];

    int p = beg;
    for (; p + 1 < end; p += 2) {
        const uint2 e0 = g_edge[p];
        const uint2 e1 = g_edge[p + 1];
        const float w0 = __uint_as_float(e0.y);
        const float w1 = __uint_as_float(e1.y);
        const uint4 v0 = *reinterpret_cast<const uint4*>(
            &g_supp_h[(size_t)e0.x * OUT_SIZE + lane * 8]);
        const uint4 v1 = *reinterpret_cast<const uint4*>(
            &g_supp_h[(size_t)e1.x * OUT_SIZE + lane * 8]);

        float2 f;
        f = h2f2(v0.x); acc0.x = fmaf(f.x, w0, acc0.x); acc0.y = fmaf(f.y, w0, acc0.y);
        f = h2f2(v0.y); acc0.z = fmaf(f.x, w0, acc0.z); acc0.w = fmaf(f.y, w0, acc0.w);
        f = h2f2(v0.z); acc1.x = fmaf(f.x, w0, acc1.x); acc1.y = fmaf(f.y, w0, acc1.y);
        f = h2f2(v0.w); acc1.z = fmaf(f.x, w0, acc1.z); acc1.w = fmaf(f.y, w0, acc1.w);

        f = h2f2(v1.x); acc0.x = fmaf(f.x, w1, acc0.x); acc0.y = fmaf(f.y, w1, acc0.y);
        f = h2f2(v1.y); acc0.z = fmaf(f.x, w1, acc0.z); acc0.w = fmaf(f.y, w1, acc0.w);
        f = h2f2(v1.z); acc1.x = fmaf(f.x, w1, acc1.x); acc1.y = fmaf(f.y, w1, acc1.y);
        f = h2f2(v1.w); acc1.z = fmaf(f.x, w1, acc1.z); acc1.w = fmaf(f.y, w1, acc1.w);
    }
    if (p < end) {
        const uint2 e0 = g_edge[p];
        const float w0 = __uint_as_float(e0.y);
        const uint4 v0 = *reinterpret_cast<const uint4*>(
            &g_supp_h[(size_t)e0.x * OUT_SIZE + lane * 8]);
        float2 f;
        f = h2f2(v0.x); acc0.x = fmaf(f.x, w0, acc0.x); acc0.y = fmaf(f.y, w0, acc0.y);
        f = h2f2(v0.y); acc0.z = fmaf(f.x, w0, acc0.z); acc0.w = fmaf(f.y, w0, acc0.w);
        f = h2f2(v0.z); acc1.x = fmaf(f.x, w0, acc1.x); acc1.y = fmaf(f.y, w0, acc1.y);
        f = h2f2(v0.w); acc1.z = fmaf(f.x, w0, acc1.z); acc1.w = fmaf(f.y, w0, acc1.w);
    }

    float* op = &out[(size_t)d * OUT_SIZE + lane * 8];
    stcs_f4(op, acc0);
    stcs_f4(op + 4, acc1);
}

// ---------------------------------------------------------------------------
extern "C" void kernel_launch(void* const* d_in, const int* in_sizes, int n_in,
                              void* d_out, int out_size) {
    const float* x      = (const float*)d_in[0];
    const float* weight = (const float*)d_in[1];
    const float* bias   = (const float*)d_in[2];
    const float* ew     = (const float*)d_in[3];
    const int*   esrc   = (const int*)d_in[4];
    const int*   edst   = (const int*)d_in[5];
    float* out = (float*)d_out;

    static cudaStream_t s2 = nullptr, s3 = nullptr;
    static cudaEvent_t evA = nullptr, evB = nullptr, evG = nullptr;
    static cudaEvent_t evP[4] = {nullptr, nullptr, nullptr, nullptr};
    if (!s2) {
        cudaStreamCreateWithFlags(&s2, cudaStreamNonBlocking);
        cudaStreamCreateWithFlags(&s3, cudaStreamNonBlocking);
        cudaEventCreateWithFlags(&evA, cudaEventDisableTiming);
        cudaEventCreateWithFlags(&evB, cudaEventDisableTiming);
        cudaEventCreateWithFlags(&evG, cudaEventDisableTiming);
        for (int i = 0; i < 4; i++) cudaEventCreateWithFlags(&evP[i], cudaEventDisableTiming);
        cudaFuncSetAttribute(gemm_hmma_kernel, cudaFuncAttributeMaxDynamicSharedMemorySize,
                             GEMM_SMEM);
    }

    cudaEventRecord(evA, 0);
    cudaStreamWaitEvent(s2, evA, 0);
    cudaStreamWaitEvent(s3, evA, 0);

    // ---- main: staged X (and W) conversion, 4 slices
    prep_xw_kernel<<<(S0_F4 + W_F4) / 256, 256>>>(x, weight);               // 1 main
    cudaEventRecord(evP[0], 0);
    prep_x_kernel<<<S1_F4 / 256, 256>>>(x, S0_F4);                          // 2 main
    cudaEventRecord(evP[1], 0);

    zero_deg_kernel<<<(N_NODES + 255) / 256, 256, 0, s2>>>();               // 3 s2

    // ---- s3: gemm slices chained, each gated on its prep slice
    cudaStreamWaitEvent(s3, evP[0], 0);
    dim3 g196(OUT_SIZE / 128, 196), g194(OUT_SIZE / 128, 194);
    gemm_hmma_kernel<<<g196, 256, GEMM_SMEM, s3>>>(0);                      // 4 s3 (profiled)

    prep_x_kernel<<<S2_F4 / 256, 256>>>(x, S0_F4 + S1_F4);                  // 5 main
    cudaEventRecord(evP[2], 0);
    cudaStreamWaitEvent(s3, evP[1], 0);
    gemm_hmma_kernel<<<g196, 256, GEMM_SMEM, s3>>>(S0_ROWS);                // 6 s3

    prep_x_kernel<<<S3_F4 / 256, 256>>>(x, S0_F4 + S1_F4 + S2_F4);          // 7 main
    cudaEventRecord(evP[3], 0);
    cudaStreamWaitEvent(s3, evP[2], 0);
    gemm_hmma_kernel<<<g196, 256, GEMM_SMEM, s3>>>(S0_ROWS + S1_ROWS);      // 8 s3

    // ---- s2: CSR chain
    hist_kernel<<<(N_EDGES + 255) / 256, 256, 0, s2>>>(edst);
    scan1_kernel<<<NBLK_SCAN, 1024, 0, s2>>>();
    scan2_kernel<<<1, 128, 0, s2>>>();
    scan3_kernel<<<(N_NODES + 255) / 256, 256, 0, s2>>>();
    fill_kernel<<<(N_EDGES + 255) / 256, 256, 0, s2>>>(ew, esrc, edst);
    cudaEventRecord(evB, s2);

    // ---- s3: last gemm slice
    cudaStreamWaitEvent(s3, evP[3], 0);
    gemm_hmma_kernel<<<g194, 256, GEMM_SMEM, s3>>>(S0_ROWS + S1_ROWS + S2_ROWS);
    cudaEventRecord(evG, s3);

    // ---- main: aggregate after all gemms + CSR
    cudaStreamWaitEvent(0, evB, 0);
    cudaStreamWaitEvent(0, evG, 0);
    aggregate_kernel<<<(N_NODES * 32 + 255) / 256, 256>>>(bias, out);
}